// round 1
// baseline (speedup 1.0000x reference)
#include <cuda_runtime.h>
#include <math.h>

#define NN 50000
#define NE 800000
#define NG 256
#define LN2F 0.69314718055994531f

// ---------------- scratch (device globals; no allocation allowed) ----------------
__device__ float g_h  [NN * 64];    // node features
__device__ float g_hs [NN * 128];   // h @ W1[0:64]   (src half)
__device__ float g_hd [NN * 128];   // h @ W1[64:128] (dst half)
__device__ float g_agg[NN * 64];    // scatter accumulator
__device__ float g_e  [NE * 64];    // edge features (updated in place)
__device__ float g_sums[NG];
__device__ float g_cnt [NG];

__device__ __forceinline__ float ssp_f(float x) {
    // softplus(x) - ln2, numerically stable
    return fmaxf(x, 0.0f) + __logf(1.0f + __expf(-fabsf(x))) - LN2F;
}

// ---------------- init ----------------
__global__ void k_init_nodes(const int* __restrict__ az, const float* __restrict__ emb) {
    int t = blockIdx.x * blockDim.x + threadIdx.x;
    if (t >= NN * 16) return;
    int n = t >> 4, q = t & 15;
    int z = az[n];
    float4 v = ((const float4*)(emb + (size_t)z * 64))[q];
    ((float4*)(g_h + (size_t)n * 64))[q] = v;
    ((float4*)(g_agg + (size_t)n * 64))[q] = make_float4(0.f, 0.f, 0.f, 0.f);
}

__global__ void k_init_edges(const float* __restrict__ dist) {
    int t = blockIdx.x * blockDim.x + threadIdx.x;
    if (t >= NE * 64) return;
    int e = t >> 6, j = t & 63;
    float d = dist[e];
    float c = (5.0f / 63.0f) * (float)j;
    float df = d - c;
    g_e[t] = __expf(-df * df * (63.0f / 5.0f));
}

__global__ void k_zero_pool() {
    int t = threadIdx.x;
    if (t < NG) { g_sums[t] = 0.f; g_cnt[t] = 0.f; }
}

// ---------------- per-layer node precompute: hs = h@W1a, hd = h@W1b ----------------
__global__ void __launch_bounds__(256) k_node_pre(const float* __restrict__ w1) {
    extern __shared__ float sm[];  // 64 x 256: [k][j<128]=W1[k][j], [k][j>=128]=W1[64+k][j-128]
    int tid = threadIdx.x;
    for (int i = tid; i < 16384; i += 256) {
        int k = i >> 8, j = i & 255;
        sm[i] = (j < 128) ? w1[k * 128 + j] : w1[(64 + k) * 128 + (j - 128)];
    }
    __syncthreads();
    int lane = tid & 31, warp = tid >> 5;
    int nw = gridDim.x * 8;
    const float* ws = sm + 4 * lane;
    for (int n = blockIdx.x * 8 + warp; n < NN; n += nw) {
        float2 hv = *(const float2*)(g_h + (size_t)n * 64 + 2 * lane);
        float4 as = make_float4(0.f, 0.f, 0.f, 0.f);
        float4 ad = make_float4(0.f, 0.f, 0.f, 0.f);
#pragma unroll 8
        for (int k = 0; k < 64; k++) {
            float hk = __shfl_sync(0xffffffffu, (k & 1) ? hv.y : hv.x, k >> 1);
            float4 w0 = *(const float4*)(ws + k * 256);
            float4 w1r = *(const float4*)(ws + k * 256 + 128);
            as.x = fmaf(hk, w0.x, as.x);  as.y = fmaf(hk, w0.y, as.y);
            as.z = fmaf(hk, w0.z, as.z);  as.w = fmaf(hk, w0.w, as.w);
            ad.x = fmaf(hk, w1r.x, ad.x); ad.y = fmaf(hk, w1r.y, ad.y);
            ad.z = fmaf(hk, w1r.z, ad.z); ad.w = fmaf(hk, w1r.w, ad.w);
        }
        *(float4*)(g_hs + (size_t)n * 128 + 4 * lane) = as;
        *(float4*)(g_hd + (size_t)n * 128 + 4 * lane) = ad;
    }
}

// ---------------- fused edge kernel (the hot one) ----------------
// smem floats: W1c 8192 | W2 8192 | P1 4096 | P2 4096 | b1 128 | b2 64 | pb1 64 | pb2 64 | scr 1024
#define EDGE_SMEM_FLOATS 25920
__global__ void __launch_bounds__(256) k_edge(
    const int* __restrict__ src, const int* __restrict__ dst,
    const float* __restrict__ w1c, const float* __restrict__ b1,
    const float* __restrict__ w2,  const float* __restrict__ b2,
    const float* __restrict__ p1,  const float* __restrict__ pb1,
    const float* __restrict__ p2,  const float* __restrict__ pb2)
{
    extern __shared__ float sm[];
    float* sW1 = sm;
    float* sW2 = sm + 8192;
    float* sP1 = sm + 16384;
    float* sP2 = sm + 20480;
    float* sB1 = sm + 24576;
    float* sB2 = sm + 24704;
    float* sQ1 = sm + 24768;
    float* sQ2 = sm + 24832;
    float* scr = sm + 24896;

    int tid = threadIdx.x;
    for (int i = tid; i < 8192; i += 256) { sW1[i] = w1c[i]; sW2[i] = w2[i]; }
    for (int i = tid; i < 4096; i += 256) { sP1[i] = p1[i];  sP2[i] = p2[i]; }
    if (tid < 128) sB1[tid] = b1[tid];
    if (tid < 64) { sB2[tid] = b2[tid]; sQ1[tid] = pb1[tid]; sQ2[tid] = pb2[tid]; }
    __syncthreads();

    int lane = tid & 31, warp = tid >> 5;
    float* myscr = scr + warp * 128;
    const float* w1p = sW1 + 4 * lane;
    const float* w2p = sW2 + 2 * lane;
    const float* p1p = sP1 + 2 * lane;
    const float* p2p = sP2 + 2 * lane;
    int nw = gridDim.x * 8;

    for (int e = blockIdx.x * 8 + warp; e < NE; e += nw) {
        int s = src[e], d = dst[e];
        float2 ev = *(const float2*)(g_e + (size_t)e * 64 + 2 * lane);
        float4 ga = *(const float4*)(g_hs + (size_t)s * 128 + 4 * lane);
        float4 gb = *(const float4*)(g_hd + (size_t)d * 128 + 4 * lane);
        float4 bb = *(const float4*)(sB1 + 4 * lane);
        float4 a1;
        a1.x = ga.x + gb.x + bb.x; a1.y = ga.y + gb.y + bb.y;
        a1.z = ga.z + gb.z + bb.z; a1.w = ga.w + gb.w + bb.w;
        // stage 1: t1 = ssp(g + e @ W1c + b1)   [128], lane owns cols 4l..4l+3
#pragma unroll 8
        for (int k = 0; k < 64; k++) {
            float ek = __shfl_sync(0xffffffffu, (k & 1) ? ev.y : ev.x, k >> 1);
            float4 w = *(const float4*)(w1p + k * 128);
            a1.x = fmaf(ek, w.x, a1.x); a1.y = fmaf(ek, w.y, a1.y);
            a1.z = fmaf(ek, w.z, a1.z); a1.w = fmaf(ek, w.w, a1.w);
        }
        a1.x = ssp_f(a1.x); a1.y = ssp_f(a1.y); a1.z = ssp_f(a1.z); a1.w = ssp_f(a1.w);
        *(float4*)(myscr + 4 * lane) = a1;
        __syncwarp();
        // stage 2: e' = t1 @ W2 + b2   [64], lane owns cols 2l,2l+1
        float2 a2 = *(const float2*)(sB2 + 2 * lane);
#pragma unroll 8
        for (int k = 0; k < 128; k += 4) {
            float4 t = *(const float4*)(myscr + k);     // broadcast
            float2 q0 = *(const float2*)(w2p + (k + 0) * 64);
            float2 q1 = *(const float2*)(w2p + (k + 1) * 64);
            float2 q2 = *(const float2*)(w2p + (k + 2) * 64);
            float2 q3 = *(const float2*)(w2p + (k + 3) * 64);
            a2.x = fmaf(t.x, q0.x, a2.x); a2.y = fmaf(t.x, q0.y, a2.y);
            a2.x = fmaf(t.y, q1.x, a2.x); a2.y = fmaf(t.y, q1.y, a2.y);
            a2.x = fmaf(t.z, q2.x, a2.x); a2.y = fmaf(t.z, q2.y, a2.y);
            a2.x = fmaf(t.w, q3.x, a2.x); a2.y = fmaf(t.w, q3.y, a2.y);
        }
        __syncwarp();
        *(float2*)(g_e + (size_t)e * 64 + 2 * lane) = a2;   // new edge features
        // stage 3: t2 = ssp(e' @ P1 + pb1)
        float2 a3 = *(const float2*)(sQ1 + 2 * lane);
#pragma unroll 8
        for (int k = 0; k < 64; k++) {
            float ek = __shfl_sync(0xffffffffu, (k & 1) ? a2.y : a2.x, k >> 1);
            float2 w = *(const float2*)(p1p + k * 64);
            a3.x = fmaf(ek, w.x, a3.x); a3.y = fmaf(ek, w.y, a3.y);
        }
        a3.x = ssp_f(a3.x); a3.y = ssp_f(a3.y);
        // stage 4: he = t2 @ P2 + pb2
        float2 a4 = *(const float2*)(sQ2 + 2 * lane);
#pragma unroll 8
        for (int k = 0; k < 64; k++) {
            float ek = __shfl_sync(0xffffffffu, (k & 1) ? a3.y : a3.x, k >> 1);
            float2 w = *(const float2*)(p2p + k * 64);
            a4.x = fmaf(ek, w.x, a4.x); a4.y = fmaf(ek, w.y, a4.y);
        }
        // scatter-add into agg[dst]
        float* dp = g_agg + (size_t)d * 64 + 2 * lane;
        asm volatile("red.global.add.v2.f32 [%0], {%1, %2};" :: "l"(dp), "f"(a4.x), "f"(a4.y) : "memory");
    }
}

// ---------------- per-layer node update: h += ssp(agg@A+ab)@B + bb; agg=0 ----------------
__global__ void __launch_bounds__(256) k_node_post(
    const float* __restrict__ wa, const float* __restrict__ ba,
    const float* __restrict__ wb, const float* __restrict__ bb_)
{
    __shared__ float sA[4096], sB[4096], sBa[64], sBb[64];
    int tid = threadIdx.x;
    for (int i = tid; i < 4096; i += 256) { sA[i] = wa[i]; sB[i] = wb[i]; }
    if (tid < 64) { sBa[tid] = ba[tid]; sBb[tid] = bb_[tid]; }
    __syncthreads();
    int lane = tid & 31, warp = tid >> 5;
    int nw = gridDim.x * 8;
    for (int n = blockIdx.x * 8 + warp; n < NN; n += nw) {
        float2 av = *(const float2*)(g_agg + (size_t)n * 64 + 2 * lane);
        *(float2*)(g_agg + (size_t)n * 64 + 2 * lane) = make_float2(0.f, 0.f);
        float2 a = *(const float2*)(sBa + 2 * lane);
#pragma unroll 8
        for (int k = 0; k < 64; k++) {
            float ek = __shfl_sync(0xffffffffu, (k & 1) ? av.y : av.x, k >> 1);
            float2 w = *(const float2*)(sA + k * 64 + 2 * lane);
            a.x = fmaf(ek, w.x, a.x); a.y = fmaf(ek, w.y, a.y);
        }
        a.x = ssp_f(a.x); a.y = ssp_f(a.y);
        float2 o = *(const float2*)(sBb + 2 * lane);
#pragma unroll 8
        for (int k = 0; k < 64; k++) {
            float ek = __shfl_sync(0xffffffffu, (k & 1) ? a.y : a.x, k >> 1);
            float2 w = *(const float2*)(sB + k * 64 + 2 * lane);
            o.x = fmaf(ek, w.x, o.x); o.y = fmaf(ek, w.y, o.y);
        }
        float2 hv = *(const float2*)(g_h + (size_t)n * 64 + 2 * lane);
        hv.x += o.x; hv.y += o.y;
        *(float2*)(g_h + (size_t)n * 64 + 2 * lane) = hv;
    }
}

// ---------------- readout + per-graph mean ----------------
__global__ void __launch_bounds__(256) k_readout(
    const int* __restrict__ gid,
    const float* __restrict__ d1w, const float* __restrict__ d1b,
    const float* __restrict__ d2w, const float* __restrict__ d2b)
{
    __shared__ float sW[2048], sB1r[32], sW2r[32];
    __shared__ float sB2r;
    int tid = threadIdx.x;
    for (int i = tid; i < 2048; i += 256) sW[i] = d1w[i];
    if (tid < 32) { sB1r[tid] = d1b[tid]; sW2r[tid] = d2w[tid]; }
    if (tid == 0) sB2r = d2b[0];
    __syncthreads();
    int lane = tid & 31, warp = tid >> 5;
    int nw = gridDim.x * 8;
    for (int n = blockIdx.x * 8 + warp; n < NN; n += nw) {
        float2 hv = *(const float2*)(g_h + (size_t)n * 64 + 2 * lane);
        float a = sB1r[lane];
#pragma unroll 8
        for (int k = 0; k < 64; k++) {
            float ek = __shfl_sync(0xffffffffu, (k & 1) ? hv.y : hv.x, k >> 1);
            a = fmaf(ek, sW[k * 32 + lane], a);
        }
        float p = ssp_f(a) * sW2r[lane];
#pragma unroll
        for (int off = 16; off; off >>= 1) p += __shfl_xor_sync(0xffffffffu, p, off);
        if (lane == 0) {
            int g = gid[n];
            atomicAdd(&g_sums[g], p + sB2r);
            atomicAdd(&g_cnt[g], 1.0f);
        }
    }
}

__global__ void k_final(float* __restrict__ out) {
    int t = threadIdx.x;
    if (t < NG) out[t] = g_sums[t] / fmaxf(g_cnt[t], 1.0f);
}

// ---------------- launch ----------------
extern "C" void kernel_launch(void* const* d_in, const int* in_sizes, int n_in,
                              void* d_out, int out_size) {
    const int*   az     = (const int*)d_in[0];
    const float* dist   = (const float*)d_in[1];
    const int*   src    = (const int*)d_in[2];
    const int*   dst    = (const int*)d_in[3];
    const int*   gid    = (const int*)d_in[4];
    const float* emb    = (const float*)d_in[5];
    const float* eu_w1  = (const float*)d_in[6];
    const float* eu_b1  = (const float*)d_in[7];
    const float* eu_w2  = (const float*)d_in[8];
    const float* eu_b2  = (const float*)d_in[9];
    const float* pe1_w  = (const float*)d_in[10];
    const float* pe1_b  = (const float*)d_in[11];
    const float* pe2_w  = (const float*)d_in[12];
    const float* pe2_b  = (const float*)d_in[13];
    const float* pn2a_w = (const float*)d_in[14];
    const float* pn2a_b = (const float*)d_in[15];
    const float* pn2b_w = (const float*)d_in[16];
    const float* pn2b_b = (const float*)d_in[17];
    const float* d1w    = (const float*)d_in[18];
    const float* d1b    = (const float*)d_in[19];
    const float* d2w    = (const float*)d_in[20];
    const float* d2b    = (const float*)d_in[21];

    cudaFuncSetAttribute(k_edge, cudaFuncAttributeMaxDynamicSharedMemorySize, EDGE_SMEM_FLOATS * 4);
    cudaFuncSetAttribute(k_node_pre, cudaFuncAttributeMaxDynamicSharedMemorySize, 16384 * 4);

    k_init_nodes<<<(NN * 16 + 255) / 256, 256>>>(az, emb);
    k_init_edges<<<(NE * 64 + 255) / 256, 256>>>(dist);
    k_zero_pool<<<1, 256>>>();

    for (int l = 0; l < 3; l++) {
        k_node_pre<<<296, 256, 16384 * 4>>>(eu_w1 + (size_t)l * 24576);
        k_edge<<<296, 256, EDGE_SMEM_FLOATS * 4>>>(
            src, dst,
            eu_w1 + (size_t)l * 24576 + 16384, eu_b1 + l * 128,
            eu_w2 + (size_t)l * 8192,          eu_b2 + l * 64,
            pe1_w + (size_t)l * 4096,          pe1_b + l * 64,
            pe2_w + (size_t)l * 4096,          pe2_b + l * 64);
        k_node_post<<<296, 256>>>(
            pn2a_w + (size_t)l * 4096, pn2a_b + l * 64,
            pn2b_w + (size_t)l * 4096, pn2b_b + l * 64);
    }
    k_readout<<<296, 256>>>(gid, d1w, d1b, d2w, d2b);
    k_final<<<1, 256>>>((float*)d_out);
}

// round 2
// speedup vs baseline: 2.2332x; 2.2332x over previous
#include <cuda_runtime.h>
#include <math.h>

#define NN 50000
#define NE 800000
#define NG 256
#define LN2F 0.69314718055994531f
#define EB 8

// ---------------- scratch (device globals; no allocation allowed) ----------------
__device__ float g_h  [NN * 64];    // node features
__device__ float g_hs [NN * 128];   // h @ W1[0:64]   (src half)
__device__ float g_hd [NN * 128];   // h @ W1[64:128] (dst half)
__device__ float g_agg[NN * 64];    // scatter accumulator
__device__ float g_e  [NE * 64];    // edge features (updated in place)
__device__ float g_sums[NG];
__device__ float g_cnt [NG];

typedef unsigned long long u64;

__device__ __forceinline__ u64 pack2(float lo, float hi) {
    u64 r; asm("mov.b64 %0, {%1, %2};" : "=l"(r) : "f"(lo), "f"(hi)); return r;
}
__device__ __forceinline__ void fma2(u64 &d, u64 a, u64 b) {
    asm("fma.rn.f32x2 %0, %1, %2, %0;" : "+l"(d) : "l"(a), "l"(b));
}
__device__ __forceinline__ float hsum2(u64 v) {
    float lo, hi; asm("mov.b64 {%0, %1}, %2;" : "=f"(lo), "=f"(hi) : "l"(v));
    return lo + hi;
}
__device__ __forceinline__ float ssp_f(float x) {
    // softplus(x) - ln2, numerically stable
    return fmaxf(x, 0.0f) + __logf(1.0f + __expf(-fabsf(x))) - LN2F;
}

// ---------------- init ----------------
__global__ void k_init_nodes(const int* __restrict__ az, const float* __restrict__ emb) {
    int t = blockIdx.x * blockDim.x + threadIdx.x;
    if (t >= NN * 16) return;
    int n = t >> 4, q = t & 15;
    int z = az[n];
    float4 v = ((const float4*)(emb + (size_t)z * 64))[q];
    ((float4*)(g_h + (size_t)n * 64))[q] = v;
    ((float4*)(g_agg + (size_t)n * 64))[q] = make_float4(0.f, 0.f, 0.f, 0.f);
}

__global__ void k_init_edges(const float* __restrict__ dist) {
    int t = blockIdx.x * blockDim.x + threadIdx.x;
    if (t >= NE * 64) return;
    int e = t >> 6, j = t & 63;
    float d = dist[e];
    float c = (5.0f / 63.0f) * (float)j;
    float df = d - c;
    g_e[t] = __expf(-df * df * (63.0f / 5.0f));
}

__global__ void k_zero_pool() {
    int t = threadIdx.x;
    if (t < NG) { g_sums[t] = 0.f; g_cnt[t] = 0.f; }
}

// ---------------- per-layer node precompute: hs = h@W1a, hd = h@W1b ----------------
__global__ void __launch_bounds__(256) k_node_pre(const float* __restrict__ w1) {
    extern __shared__ float sm[];  // 64 x 256: [k][j<128]=W1[k][j], [k][j>=128]=W1[64+k][j-128]
    int tid = threadIdx.x;
    for (int i = tid; i < 16384; i += 256) {
        int k = i >> 8, j = i & 255;
        sm[i] = (j < 128) ? w1[k * 128 + j] : w1[(64 + k) * 128 + (j - 128)];
    }
    __syncthreads();
    int lane = tid & 31, warp = tid >> 5;
    int nw = gridDim.x * 8;
    const float* ws = sm + 4 * lane;
    for (int n = blockIdx.x * 8 + warp; n < NN; n += nw) {
        float2 hv = *(const float2*)(g_h + (size_t)n * 64 + 2 * lane);
        float4 as = make_float4(0.f, 0.f, 0.f, 0.f);
        float4 ad = make_float4(0.f, 0.f, 0.f, 0.f);
#pragma unroll 8
        for (int k = 0; k < 64; k++) {
            float hk = __shfl_sync(0xffffffffu, (k & 1) ? hv.y : hv.x, k >> 1);
            float4 w0 = *(const float4*)(ws + k * 256);
            float4 w1r = *(const float4*)(ws + k * 256 + 128);
            as.x = fmaf(hk, w0.x, as.x);  as.y = fmaf(hk, w0.y, as.y);
            as.z = fmaf(hk, w0.z, as.z);  as.w = fmaf(hk, w0.w, as.w);
            ad.x = fmaf(hk, w1r.x, ad.x); ad.y = fmaf(hk, w1r.y, ad.y);
            ad.z = fmaf(hk, w1r.z, ad.z); ad.w = fmaf(hk, w1r.w, ad.w);
        }
        *(float4*)(g_hs + (size_t)n * 128 + 4 * lane) = as;
        *(float4*)(g_hd + (size_t)n * 128 + 4 * lane) = ad;
    }
}

// ---------------- fused edge kernel (register-blocked, packed f32x2) ----------------
// smem floats:
//   sW1T [128][68]  = 8704   @ 0       (W1c transposed, pad 64->68, stride%32==4)
//   sW2T [64][132]  = 8448   @ 8704    (W2 transposed, pad 128->132)
//   sP1T [64][68]   = 4352   @ 17152
//   sP2T [64][68]   = 4352   @ 21504
//   b1 128 @25856 | b2 64 @25984 | q1 64 @26048 | q2 64 @26112
//   scratch 8 warps x 1024 @ 26176
#define EDGE_SMEM_FLOATS (26176 + 8 * 1024)
__global__ void __launch_bounds__(256, 1) k_edge(
    const int* __restrict__ src, const int* __restrict__ dst,
    const float* __restrict__ w1c, const float* __restrict__ b1,
    const float* __restrict__ w2,  const float* __restrict__ b2,
    const float* __restrict__ p1,  const float* __restrict__ pb1,
    const float* __restrict__ p2,  const float* __restrict__ pb2)
{
    extern __shared__ float sm[];
    float* sW1T = sm;
    float* sW2T = sm + 8704;
    float* sP1T = sm + 17152;
    float* sP2T = sm + 21504;
    float* sB1  = sm + 25856;
    float* sB2  = sm + 25984;
    float* sQ1  = sm + 26048;
    float* sQ2  = sm + 26112;
    float* sScr = sm + 26176;

    int tid = threadIdx.x;
    // load + transpose weights: sXT[c*stride + k] = w[k*C + c]
    for (int i = tid; i < 8192; i += 256) { int k = i >> 7, c = i & 127; sW1T[c * 68 + k] = w1c[i]; }
    for (int i = tid; i < 8192; i += 256) { int k = i >> 6, c = i & 63;  sW2T[c * 132 + k] = w2[i]; }
    for (int i = tid; i < 4096; i += 256) { int k = i >> 6, c = i & 63;  sP1T[c * 68 + k] = p1[i]; sP2T[c * 68 + k] = p2[i]; }
    if (tid < 128) sB1[tid] = b1[tid];
    if (tid < 64) { sB2[tid] = b2[tid]; sQ1[tid] = pb1[tid]; sQ2[tid] = pb2[tid]; }
    __syncthreads();

    int lane = tid & 31, warp = tid >> 5;
    float* scr = sScr + warp * 1024;
    const int c0 = lane, c1 = lane + 32, c2 = lane + 64, c3 = lane + 96;

    const float b1v0 = sB1[c0], b1v1 = sB1[c1], b1v2 = sB1[c2], b1v3 = sB1[c3];
    const float b2v0 = sB2[c0], b2v1 = sB2[c1];
    const float q1v0 = sQ1[c0], q1v1 = sQ1[c1];
    const float q2v0 = sQ2[c0], q2v1 = sQ2[c1];

    const float* w1p0 = sW1T + c0 * 68;
    const float* w1p1 = sW1T + c1 * 68;
    const float* w1p2 = sW1T + c2 * 68;
    const float* w1p3 = sW1T + c3 * 68;
    const float* w2p0 = sW2T + c0 * 132;
    const float* w2p1 = sW2T + c1 * 132;
    const float* p1p0 = sP1T + c0 * 68;
    const float* p1p1 = sP1T + c1 * 68;
    const float* p2p0 = sP2T + c0 * 68;
    const float* p2p1 = sP2T + c1 * 68;

    const int ngrp = NE / EB;           // 100000, exact
    const int stride = gridDim.x * 8;

    for (int g = blockIdx.x * 8 + warp; g < ngrp; g += stride) {
        const int base = g * EB;
        int s[EB], d[EB];
#pragma unroll
        for (int i = 0; i < EB; i++) { s[i] = __ldg(src + base + i); d[i] = __ldg(dst + base + i); }

        // ================= stage 1: t1 = ssp(hs[s]+hd[d]+b1 + e@W1c) [128] =================
        u64 acc[EB][4];
#pragma unroll
        for (int i = 0; i < EB; i++) {
            const float* hs = g_hs + (size_t)s[i] * 128;
            const float* hd = g_hd + (size_t)d[i] * 128;
            acc[i][0] = pack2(hs[c0] + hd[c0] + b1v0, 0.f);
            acc[i][1] = pack2(hs[c1] + hd[c1] + b1v1, 0.f);
            acc[i][2] = pack2(hs[c2] + hd[c2] + b1v2, 0.f);
            acc[i][3] = pack2(hs[c3] + hd[c3] + b1v3, 0.f);
        }
#pragma unroll 2
        for (int k = 0; k < 64; k += 4) {
            ulonglong2 wa = *(const ulonglong2*)(w1p0 + k);
            ulonglong2 wb = *(const ulonglong2*)(w1p1 + k);
            ulonglong2 wc = *(const ulonglong2*)(w1p2 + k);
            ulonglong2 wd = *(const ulonglong2*)(w1p3 + k);
#pragma unroll
            for (int i = 0; i < EB; i++) {
                ulonglong2 ev = *(const ulonglong2*)(g_e + (size_t)(base + i) * 64 + k); // broadcast
                fma2(acc[i][0], ev.x, wa.x); fma2(acc[i][0], ev.y, wa.y);
                fma2(acc[i][1], ev.x, wb.x); fma2(acc[i][1], ev.y, wb.y);
                fma2(acc[i][2], ev.x, wc.x); fma2(acc[i][2], ev.y, wc.y);
                fma2(acc[i][3], ev.x, wd.x); fma2(acc[i][3], ev.y, wd.y);
            }
        }
#pragma unroll
        for (int i = 0; i < EB; i++) {
            scr[i * 128 + c0] = ssp_f(hsum2(acc[i][0]));
            scr[i * 128 + c1] = ssp_f(hsum2(acc[i][1]));
            scr[i * 128 + c2] = ssp_f(hsum2(acc[i][2]));
            scr[i * 128 + c3] = ssp_f(hsum2(acc[i][3]));
        }
        __syncwarp();

        // ================= stage 2: e' = t1 @ W2 + b2 [64] =================
        u64 a2[EB][2];
#pragma unroll
        for (int i = 0; i < EB; i++) { a2[i][0] = pack2(b2v0, 0.f); a2[i][1] = pack2(b2v1, 0.f); }
#pragma unroll 2
        for (int k = 0; k < 128; k += 4) {
            ulonglong2 wa = *(const ulonglong2*)(w2p0 + k);
            ulonglong2 wb = *(const ulonglong2*)(w2p1 + k);
#pragma unroll
            for (int i = 0; i < EB; i++) {
                ulonglong2 t = *(const ulonglong2*)(scr + i * 128 + k);   // broadcast
                fma2(a2[i][0], t.x, wa.x); fma2(a2[i][0], t.y, wa.y);
                fma2(a2[i][1], t.x, wb.x); fma2(a2[i][1], t.y, wb.y);
            }
        }
        __syncwarp();
#pragma unroll
        for (int i = 0; i < EB; i++) {
            float e0 = hsum2(a2[i][0]);
            float e1 = hsum2(a2[i][1]);
            scr[i * 64 + c0] = e0;                     // e' scratch (overwrites t1, reads done)
            scr[i * 64 + c1] = e1;
            g_e[(size_t)(base + i) * 64 + c0] = e0;    // new edge features
            g_e[(size_t)(base + i) * 64 + c1] = e1;
        }
        __syncwarp();

        // ================= stage 3: t2 = ssp(e' @ P1 + pb1) [64] =================
        u64 a3[EB][2];
#pragma unroll
        for (int i = 0; i < EB; i++) { a3[i][0] = pack2(q1v0, 0.f); a3[i][1] = pack2(q1v1, 0.f); }
#pragma unroll 2
        for (int k = 0; k < 64; k += 4) {
            ulonglong2 wa = *(const ulonglong2*)(p1p0 + k);
            ulonglong2 wb = *(const ulonglong2*)(p1p1 + k);
#pragma unroll
            for (int i = 0; i < EB; i++) {
                ulonglong2 t = *(const ulonglong2*)(scr + i * 64 + k);    // broadcast
                fma2(a3[i][0], t.x, wa.x); fma2(a3[i][0], t.y, wa.y);
                fma2(a3[i][1], t.x, wb.x); fma2(a3[i][1], t.y, wb.y);
            }
        }
#pragma unroll
        for (int i = 0; i < EB; i++) {
            scr[512 + i * 64 + c0] = ssp_f(hsum2(a3[i][0]));
            scr[512 + i * 64 + c1] = ssp_f(hsum2(a3[i][1]));
        }
        __syncwarp();

        // ================= stage 4: he = t2 @ P2 + pb2; scatter-add =================
        u64 a4[EB][2];
#pragma unroll
        for (int i = 0; i < EB; i++) { a4[i][0] = pack2(q2v0, 0.f); a4[i][1] = pack2(q2v1, 0.f); }
#pragma unroll 2
        for (int k = 0; k < 64; k += 4) {
            ulonglong2 wa = *(const ulonglong2*)(p2p0 + k);
            ulonglong2 wb = *(const ulonglong2*)(p2p1 + k);
#pragma unroll
            for (int i = 0; i < EB; i++) {
                ulonglong2 t = *(const ulonglong2*)(scr + 512 + i * 64 + k);  // broadcast
                fma2(a4[i][0], t.x, wa.x); fma2(a4[i][0], t.y, wa.y);
                fma2(a4[i][1], t.x, wb.x); fma2(a4[i][1], t.y, wb.y);
            }
        }
#pragma unroll
        for (int i = 0; i < EB; i++) {
            float h0 = hsum2(a4[i][0]);
            float h1 = hsum2(a4[i][1]);
            float* dp = g_agg + (size_t)d[i] * 64;
            asm volatile("red.global.add.f32 [%0], %1;" :: "l"(dp + c0), "f"(h0) : "memory");
            asm volatile("red.global.add.f32 [%0], %1;" :: "l"(dp + c1), "f"(h1) : "memory");
        }
        __syncwarp();
    }
}

// ---------------- per-layer node update: h += ssp(agg@A+ab)@B + bb; agg=0 ----------------
__global__ void __launch_bounds__(256) k_node_post(
    const float* __restrict__ wa, const float* __restrict__ ba,
    const float* __restrict__ wb, const float* __restrict__ bb_)
{
    __shared__ float sA[4096], sB[4096], sBa[64], sBb[64];
    int tid = threadIdx.x;
    for (int i = tid; i < 4096; i += 256) { sA[i] = wa[i]; sB[i] = wb[i]; }
    if (tid < 64) { sBa[tid] = ba[tid]; sBb[tid] = bb_[tid]; }
    __syncthreads();
    int lane = tid & 31, warp = tid >> 5;
    int nw = gridDim.x * 8;
    for (int n = blockIdx.x * 8 + warp; n < NN; n += nw) {
        float2 av = *(const float2*)(g_agg + (size_t)n * 64 + 2 * lane);
        *(float2*)(g_agg + (size_t)n * 64 + 2 * lane) = make_float2(0.f, 0.f);
        float2 a = *(const float2*)(sBa + 2 * lane);
#pragma unroll 8
        for (int k = 0; k < 64; k++) {
            float ek = __shfl_sync(0xffffffffu, (k & 1) ? av.y : av.x, k >> 1);
            float2 w = *(const float2*)(sA + k * 64 + 2 * lane);
            a.x = fmaf(ek, w.x, a.x); a.y = fmaf(ek, w.y, a.y);
        }
        a.x = ssp_f(a.x); a.y = ssp_f(a.y);
        float2 o = *(const float2*)(sBb + 2 * lane);
#pragma unroll 8
        for (int k = 0; k < 64; k++) {
            float ek = __shfl_sync(0xffffffffu, (k & 1) ? a.y : a.x, k >> 1);
            float2 w = *(const float2*)(sB + k * 64 + 2 * lane);
            o.x = fmaf(ek, w.x, o.x); o.y = fmaf(ek, w.y, o.y);
        }
        float2 hv = *(const float2*)(g_h + (size_t)n * 64 + 2 * lane);
        hv.x += o.x; hv.y += o.y;
        *(float2*)(g_h + (size_t)n * 64 + 2 * lane) = hv;
    }
}

// ---------------- readout + per-graph mean ----------------
__global__ void __launch_bounds__(256) k_readout(
    const int* __restrict__ gid,
    const float* __restrict__ d1w, const float* __restrict__ d1b,
    const float* __restrict__ d2w, const float* __restrict__ d2b)
{
    __shared__ float sW[2048], sB1r[32], sW2r[32];
    __shared__ float sB2r;
    int tid = threadIdx.x;
    for (int i = tid; i < 2048; i += 256) sW[i] = d1w[i];
    if (tid < 32) { sB1r[tid] = d1b[tid]; sW2r[tid] = d2w[tid]; }
    if (tid == 0) sB2r = d2b[0];
    __syncthreads();
    int lane = tid & 31, warp = tid >> 5;
    int nw = gridDim.x * 8;
    for (int n = blockIdx.x * 8 + warp; n < NN; n += nw) {
        float2 hv = *(const float2*)(g_h + (size_t)n * 64 + 2 * lane);
        float a = sB1r[lane];
#pragma unroll 8
        for (int k = 0; k < 64; k++) {
            float ek = __shfl_sync(0xffffffffu, (k & 1) ? hv.y : hv.x, k >> 1);
            a = fmaf(ek, sW[k * 32 + lane], a);
        }
        float p = ssp_f(a) * sW2r[lane];
#pragma unroll
        for (int off = 16; off; off >>= 1) p += __shfl_xor_sync(0xffffffffu, p, off);
        if (lane == 0) {
            int g = gid[n];
            atomicAdd(&g_sums[g], p + sB2r);
            atomicAdd(&g_cnt[g], 1.0f);
        }
    }
}

__global__ void k_final(float* __restrict__ out) {
    int t = threadIdx.x;
    if (t < NG) out[t] = g_sums[t] / fmaxf(g_cnt[t], 1.0f);
}

// ---------------- launch ----------------
extern "C" void kernel_launch(void* const* d_in, const int* in_sizes, int n_in,
                              void* d_out, int out_size) {
    const int*   az     = (const int*)d_in[0];
    const float* dist   = (const float*)d_in[1];
    const int*   src    = (const int*)d_in[2];
    const int*   dst    = (const int*)d_in[3];
    const int*   gid    = (const int*)d_in[4];
    const float* emb    = (const float*)d_in[5];
    const float* eu_w1  = (const float*)d_in[6];
    const float* eu_b1  = (const float*)d_in[7];
    const float* eu_w2  = (const float*)d_in[8];
    const float* eu_b2  = (const float*)d_in[9];
    const float* pe1_w  = (const float*)d_in[10];
    const float* pe1_b  = (const float*)d_in[11];
    const float* pe2_w  = (const float*)d_in[12];
    const float* pe2_b  = (const float*)d_in[13];
    const float* pn2a_w = (const float*)d_in[14];
    const float* pn2a_b = (const float*)d_in[15];
    const float* pn2b_w = (const float*)d_in[16];
    const float* pn2b_b = (const float*)d_in[17];
    const float* d1w    = (const float*)d_in[18];
    const float* d1b    = (const float*)d_in[19];
    const float* d2w    = (const float*)d_in[20];
    const float* d2b    = (const float*)d_in[21];

    cudaFuncSetAttribute(k_edge, cudaFuncAttributeMaxDynamicSharedMemorySize, EDGE_SMEM_FLOATS * 4);
    cudaFuncSetAttribute(k_node_pre, cudaFuncAttributeMaxDynamicSharedMemorySize, 16384 * 4);

    k_init_nodes<<<(NN * 16 + 255) / 256, 256>>>(az, emb);
    k_init_edges<<<(NE * 64 + 255) / 256, 256>>>(dist);
    k_zero_pool<<<1, 256>>>();

    for (int l = 0; l < 3; l++) {
        k_node_pre<<<296, 256, 16384 * 4>>>(eu_w1 + (size_t)l * 24576);
        k_edge<<<148, 256, EDGE_SMEM_FLOATS * 4>>>(
            src, dst,
            eu_w1 + (size_t)l * 24576 + 16384, eu_b1 + l * 128,
            eu_w2 + (size_t)l * 8192,          eu_b2 + l * 64,
            pe1_w + (size_t)l * 4096,          pe1_b + l * 64,
            pe2_w + (size_t)l * 4096,          pe2_b + l * 64);
        k_node_post<<<296, 256>>>(
            pn2a_w + (size_t)l * 4096, pn2a_b + l * 64,
            pn2b_w + (size_t)l * 4096, pn2b_b + l * 64);
    }
    k_readout<<<296, 256>>>(gid, d1w, d1b, d2w, d2b);
    k_final<<<1, 256>>>((float*)d_out);
}

// round 3
// speedup vs baseline: 2.7215x; 1.2187x over previous
#include <cuda_runtime.h>
#include <math.h>

#define NN 50000
#define NE 800000
#define NG 256
#define LN2F 0.69314718055994531f
#define EB 8

// ---------------- scratch (device globals; no allocation allowed) ----------------
__device__ float g_h  [NN * 64];    // node features
__device__ float g_hs [NN * 128];   // h @ W1[0:64]   (src half)
__device__ float g_hd [NN * 128];   // h @ W1[64:128] (dst half)
__device__ float g_agg[NN * 64];    // scatter accumulator
__device__ float g_e  [NE * 64];    // edge features (updated in place)
__device__ float g_sums[NG];
__device__ float g_cnt [NG];

typedef unsigned long long u64;

__device__ __forceinline__ u64 pack2(float lo, float hi) {
    u64 r; asm("mov.b64 %0, {%1, %2};" : "=l"(r) : "f"(lo), "f"(hi)); return r;
}
__device__ __forceinline__ void fma2(u64 &d, u64 a, u64 b) {
    asm("fma.rn.f32x2 %0, %1, %2, %0;" : "+l"(d) : "l"(a), "l"(b));
}
__device__ __forceinline__ float hsum2(u64 v) {
    float lo, hi; asm("mov.b64 {%0, %1}, %2;" : "=f"(lo), "=f"(hi) : "l"(v));
    return lo + hi;
}
__device__ __forceinline__ float ssp_f(float x) {
    return fmaxf(x, 0.0f) + __logf(1.0f + __expf(-fabsf(x))) - LN2F;
}

// ---------------- init ----------------
__global__ void k_init_nodes(const int* __restrict__ az, const float* __restrict__ emb) {
    int t = blockIdx.x * blockDim.x + threadIdx.x;
    if (t >= NN * 16) return;
    int n = t >> 4, q = t & 15;
    int z = az[n];
    float4 v = ((const float4*)(emb + (size_t)z * 64))[q];
    ((float4*)(g_h + (size_t)n * 64))[q] = v;
    ((float4*)(g_agg + (size_t)n * 64))[q] = make_float4(0.f, 0.f, 0.f, 0.f);
}

__global__ void k_init_edges(const float* __restrict__ dist) {
    int t = blockIdx.x * blockDim.x + threadIdx.x;
    if (t >= NE * 64) return;
    int e = t >> 6, j = t & 63;
    float d = dist[e];
    float c = (5.0f / 63.0f) * (float)j;
    float df = d - c;
    g_e[t] = __expf(-df * df * (63.0f / 5.0f));
}

__global__ void k_zero_pool() {
    int t = threadIdx.x;
    if (t < NG) { g_sums[t] = 0.f; g_cnt[t] = 0.f; }
}

// ---------------- node-pre device function ----------------
// sPreT: 256 rows x 68 (rows 0..127 = W1a cols, rows 128..255 = W1b cols)
// scrN: per-warp scratch holding h for 4 nodes as [i][64]
__device__ __forceinline__ void pre_group(const float* __restrict__ sPreT,
                                          const float* __restrict__ scrN,
                                          int n0, int lane) {
#pragma unroll
    for (int half = 0; half < 2; half++) {
        u64 p[4][4];
#pragma unroll
        for (int i = 0; i < 4; i++)
#pragma unroll
            for (int j = 0; j < 4; j++) p[i][j] = 0ULL;
        const float* w0 = sPreT + (half * 128 + lane     ) * 68;
        const float* w1 = sPreT + (half * 128 + lane + 32) * 68;
        const float* w2 = sPreT + (half * 128 + lane + 64) * 68;
        const float* w3 = sPreT + (half * 128 + lane + 96) * 68;
#pragma unroll 4
        for (int k = 0; k < 64; k += 4) {
            ulonglong2 a = *(const ulonglong2*)(w0 + k);
            ulonglong2 b = *(const ulonglong2*)(w1 + k);
            ulonglong2 c = *(const ulonglong2*)(w2 + k);
            ulonglong2 d = *(const ulonglong2*)(w3 + k);
#pragma unroll
            for (int i = 0; i < 4; i++) {
                ulonglong2 t = *(const ulonglong2*)(scrN + i * 64 + k);
                fma2(p[i][0], t.x, a.x); fma2(p[i][0], t.y, a.y);
                fma2(p[i][1], t.x, b.x); fma2(p[i][1], t.y, b.y);
                fma2(p[i][2], t.x, c.x); fma2(p[i][2], t.y, c.y);
                fma2(p[i][3], t.x, d.x); fma2(p[i][3], t.y, d.y);
            }
        }
        float* out = (half == 0) ? g_hs : g_hd;
#pragma unroll
        for (int i = 0; i < 4; i++) {
            float* o = out + (size_t)(n0 + i) * 128;
            o[lane]      = hsum2(p[i][0]);
            o[lane + 32] = hsum2(p[i][1]);
            o[lane + 64] = hsum2(p[i][2]);
            o[lane + 96] = hsum2(p[i][3]);
        }
    }
}

// ---------------- layer-0 node pre ----------------
// smem: sPreT 17408 | scr 16x256 = 4096  -> 21504 floats
__global__ void __launch_bounds__(512, 1) k_pre0(const float* __restrict__ w1) {
    extern __shared__ float sm[];
    float* sPreT = sm;
    float* sScr  = sm + 17408;
    int tid = threadIdx.x;
    for (int i = tid; i < 16384; i += 512) {
        int k = i >> 7, c = i & 127;
        int row = (k < 64) ? c : (128 + c);
        sPreT[row * 68 + (k & 63)] = w1[i];
    }
    __syncthreads();
    int lane = tid & 31, warp = tid >> 5;
    float* scrN = sScr + warp * 256;
    const int stride = gridDim.x * 16;
    for (int g = blockIdx.x * 16 + warp; g < NN / 4; g += stride) {
        int n0 = g * 4;
        const float4* hsrc = (const float4*)(g_h + (size_t)n0 * 64);
        ((float4*)scrN)[lane]      = hsrc[lane];
        ((float4*)scrN)[lane + 32] = hsrc[lane + 32];
        __syncwarp();
        pre_group(sPreT, scrN, n0, lane);
        __syncwarp();
    }
}

// ---------------- fused node update: h += MLP(agg); agg=0; optional next-layer pre ----------------
// smem floats: sPreT 17408 | sAT 4352 @17408 | sBT 4352 @21760 | sBa 64 @26112 | sBb 64 @26176 | scr 16x256 @26240
#define UPD_SMEM_FLOATS 30336
__global__ void __launch_bounds__(512, 1) k_update(
    const float* __restrict__ wa, const float* __restrict__ ba,
    const float* __restrict__ wb, const float* __restrict__ bb_,
    const float* __restrict__ w1next, int do_pre)
{
    extern __shared__ float sm[];
    float* sPreT = sm;
    float* sAT   = sm + 17408;
    float* sBT   = sm + 21760;
    float* sBa   = sm + 26112;
    float* sBb   = sm + 26176;
    float* sScr  = sm + 26240;
    int tid = threadIdx.x;
    for (int i = tid; i < 4096; i += 512) {
        int k = i >> 6, c = i & 63;
        sAT[c * 68 + k] = wa[i];
        sBT[c * 68 + k] = wb[i];
    }
    if (do_pre) {
        for (int i = tid; i < 16384; i += 512) {
            int k = i >> 7, c = i & 127;
            int row = (k < 64) ? c : (128 + c);
            sPreT[row * 68 + (k & 63)] = w1next[i];
        }
    }
    if (tid < 64) { sBa[tid] = ba[tid]; sBb[tid] = bb_[tid]; }
    __syncthreads();

    int lane = tid & 31, warp = tid >> 5;
    float* scrN = sScr + warp * 256;
    const float bav0 = sBa[lane], bav1 = sBa[lane + 32];
    const float bbv0 = sBb[lane], bbv1 = sBb[lane + 32];
    const float* a0p = sAT + lane * 68;
    const float* a1p = sAT + (lane + 32) * 68;
    const float* b0p = sBT + lane * 68;
    const float* b1p = sBT + (lane + 32) * 68;
    const int stride = gridDim.x * 16;

    for (int g = blockIdx.x * 16 + warp; g < NN / 4; g += stride) {
        int n0 = g * 4;
        // preload agg into scratch; zero agg for next layer
        float4* av = (float4*)(g_agg + (size_t)n0 * 64);
        float4 z = make_float4(0.f, 0.f, 0.f, 0.f);
        float4 t0 = av[lane], t1v = av[lane + 32];
        ((float4*)scrN)[lane] = t0; ((float4*)scrN)[lane + 32] = t1v;
        av[lane] = z; av[lane + 32] = z;
        __syncwarp();
        // stage 1: a = ssp(agg @ A + ba)
        u64 aa[4][2];
#pragma unroll
        for (int i = 0; i < 4; i++) { aa[i][0] = pack2(bav0, 0.f); aa[i][1] = pack2(bav1, 0.f); }
#pragma unroll 4
        for (int k = 0; k < 64; k += 4) {
            ulonglong2 w0 = *(const ulonglong2*)(a0p + k);
            ulonglong2 w1 = *(const ulonglong2*)(a1p + k);
#pragma unroll
            for (int i = 0; i < 4; i++) {
                ulonglong2 t = *(const ulonglong2*)(scrN + i * 64 + k);
                fma2(aa[i][0], t.x, w0.x); fma2(aa[i][0], t.y, w0.y);
                fma2(aa[i][1], t.x, w1.x); fma2(aa[i][1], t.y, w1.y);
            }
        }
        __syncwarp();
#pragma unroll
        for (int i = 0; i < 4; i++) {
            scrN[i * 64 + lane]      = ssp_f(hsum2(aa[i][0]));
            scrN[i * 64 + lane + 32] = ssp_f(hsum2(aa[i][1]));
        }
        __syncwarp();
        // stage 2: h_new = h + a @ B + bb
        u64 oo[4][2];
#pragma unroll
        for (int i = 0; i < 4; i++) { oo[i][0] = pack2(bbv0, 0.f); oo[i][1] = pack2(bbv1, 0.f); }
#pragma unroll 4
        for (int k = 0; k < 64; k += 4) {
            ulonglong2 w0 = *(const ulonglong2*)(b0p + k);
            ulonglong2 w1 = *(const ulonglong2*)(b1p + k);
#pragma unroll
            for (int i = 0; i < 4; i++) {
                ulonglong2 t = *(const ulonglong2*)(scrN + i * 64 + k);
                fma2(oo[i][0], t.x, w0.x); fma2(oo[i][0], t.y, w0.y);
                fma2(oo[i][1], t.x, w1.x); fma2(oo[i][1], t.y, w1.y);
            }
        }
        __syncwarp();
#pragma unroll
        for (int i = 0; i < 4; i++) {
            float* hp = g_h + (size_t)(n0 + i) * 64;
            float h0 = hp[lane]      + hsum2(oo[i][0]);
            float h1 = hp[lane + 32] + hsum2(oo[i][1]);
            hp[lane] = h0; hp[lane + 32] = h1;
            scrN[i * 64 + lane] = h0; scrN[i * 64 + lane + 32] = h1;
        }
        __syncwarp();
        if (do_pre) { pre_group(sPreT, scrN, n0, lane); }
        __syncwarp();
    }
}

// ---------------- fused edge kernel (512 threads, e-preload, packed f32x2) ----------------
// smem floats:
//   sW1T [128][68]=8704 @0 | sW2T [64][132]=8448 @8704 | sP1T 4352 @17152 | sP2T 4352 @21504
//   b1 128 @25856 | b2 64 @25984 | q1 64 @26048 | q2 64 @26112 | scr 16 x 1024 @26176
#define EDGE_SMEM_FLOATS (26176 + 16 * 1024)
__global__ void __launch_bounds__(512, 1) k_edge(
    const int* __restrict__ src, const int* __restrict__ dst,
    const float* __restrict__ w1c, const float* __restrict__ b1,
    const float* __restrict__ w2,  const float* __restrict__ b2,
    const float* __restrict__ p1,  const float* __restrict__ pb1,
    const float* __restrict__ p2,  const float* __restrict__ pb2)
{
    extern __shared__ float sm[];
    float* sW1T = sm;
    float* sW2T = sm + 8704;
    float* sP1T = sm + 17152;
    float* sP2T = sm + 21504;
    float* sB1  = sm + 25856;
    float* sB2  = sm + 25984;
    float* sQ1  = sm + 26048;
    float* sQ2  = sm + 26112;
    float* sScr = sm + 26176;

    int tid = threadIdx.x;
    for (int i = tid; i < 8192; i += 512) { int k = i >> 7, c = i & 127; sW1T[c * 68 + k] = w1c[i]; }
    for (int i = tid; i < 8192; i += 512) { int k = i >> 6, c = i & 63;  sW2T[c * 132 + k] = w2[i]; }
    for (int i = tid; i < 4096; i += 512) { int k = i >> 6, c = i & 63;  sP1T[c * 68 + k] = p1[i]; sP2T[c * 68 + k] = p2[i]; }
    if (tid < 128) sB1[tid] = b1[tid];
    if (tid < 64) { sB2[tid] = b2[tid]; sQ1[tid] = pb1[tid]; sQ2[tid] = pb2[tid]; }
    __syncthreads();

    int lane = tid & 31, warp = tid >> 5;
    float* scr = sScr + warp * 1024;
    const int c0 = lane, c1 = lane + 32, c2 = lane + 64, c3 = lane + 96;

    const float b1v0 = sB1[c0], b1v1 = sB1[c1], b1v2 = sB1[c2], b1v3 = sB1[c3];
    const float b2v0 = sB2[c0], b2v1 = sB2[c1];
    const float q1v0 = sQ1[c0], q1v1 = sQ1[c1];
    const float q2v0 = sQ2[c0], q2v1 = sQ2[c1];

    const float* w1p0 = sW1T + c0 * 68;
    const float* w1p1 = sW1T + c1 * 68;
    const float* w1p2 = sW1T + c2 * 68;
    const float* w1p3 = sW1T + c3 * 68;
    const float* w2p0 = sW2T + c0 * 132;
    const float* w2p1 = sW2T + c1 * 132;
    const float* p1p0 = sP1T + c0 * 68;
    const float* p1p1 = sP1T + c1 * 68;
    const float* p2p0 = sP2T + c0 * 68;
    const float* p2p1 = sP2T + c1 * 68;

    const int ngrp = NE / EB;           // 100000, exact
    const int stride = gridDim.x * 16;

    for (int g = blockIdx.x * 16 + warp; g < ngrp; g += stride) {
        const int base = g * EB;
        int d[EB];
#pragma unroll
        for (int i = 0; i < EB; i++) d[i] = __ldg(dst + base + i);

        // preload e for 8 edges (512 floats) into scratch, coalesced
        {
            const float4* esrc = (const float4*)(g_e + (size_t)base * 64);
            float4* ed = (float4*)scr;
            ed[lane]      = esrc[lane];
            ed[lane + 32] = esrc[lane + 32];
            ed[lane + 64] = esrc[lane + 64];
            ed[lane + 96] = esrc[lane + 96];
        }
        __syncwarp();

        // ================= stage 1: t1 = ssp(hs[s]+hd[d]+b1 + e@W1c) [128] =================
        u64 acc[EB][4];
#pragma unroll
        for (int i = 0; i < EB; i++) {
            int s = __ldg(src + base + i);
            const float* hs = g_hs + (size_t)s * 128;
            const float* hd = g_hd + (size_t)d[i] * 128;
            acc[i][0] = pack2(hs[c0] + hd[c0] + b1v0, 0.f);
            acc[i][1] = pack2(hs[c1] + hd[c1] + b1v1, 0.f);
            acc[i][2] = pack2(hs[c2] + hd[c2] + b1v2, 0.f);
            acc[i][3] = pack2(hs[c3] + hd[c3] + b1v3, 0.f);
        }
#pragma unroll 2
        for (int k = 0; k < 64; k += 4) {
            ulonglong2 wa = *(const ulonglong2*)(w1p0 + k);
            ulonglong2 wb = *(const ulonglong2*)(w1p1 + k);
            ulonglong2 wc = *(const ulonglong2*)(w1p2 + k);
            ulonglong2 wd = *(const ulonglong2*)(w1p3 + k);
#pragma unroll
            for (int i = 0; i < EB; i++) {
                ulonglong2 ev = *(const ulonglong2*)(scr + i * 64 + k); // smem broadcast
                fma2(acc[i][0], ev.x, wa.x); fma2(acc[i][0], ev.y, wa.y);
                fma2(acc[i][1], ev.x, wb.x); fma2(acc[i][1], ev.y, wb.y);
                fma2(acc[i][2], ev.x, wc.x); fma2(acc[i][2], ev.y, wc.y);
                fma2(acc[i][3], ev.x, wd.x); fma2(acc[i][3], ev.y, wd.y);
            }
        }
        __syncwarp();   // all lanes done reading e before t1 overwrites scratch
#pragma unroll
        for (int i = 0; i < EB; i++) {
            scr[i * 128 + c0] = ssp_f(hsum2(acc[i][0]));
            scr[i * 128 + c1] = ssp_f(hsum2(acc[i][1]));
            scr[i * 128 + c2] = ssp_f(hsum2(acc[i][2]));
            scr[i * 128 + c3] = ssp_f(hsum2(acc[i][3]));
        }
        __syncwarp();

        // ================= stage 2: e' = t1 @ W2 + b2 [64] =================
        u64 a2[EB][2];
#pragma unroll
        for (int i = 0; i < EB; i++) { a2[i][0] = pack2(b2v0, 0.f); a2[i][1] = pack2(b2v1, 0.f); }
#pragma unroll 2
        for (int k = 0; k < 128; k += 4) {
            ulonglong2 wa = *(const ulonglong2*)(w2p0 + k);
            ulonglong2 wb = *(const ulonglong2*)(w2p1 + k);
#pragma unroll
            for (int i = 0; i < EB; i++) {
                ulonglong2 t = *(const ulonglong2*)(scr + i * 128 + k);
                fma2(a2[i][0], t.x, wa.x); fma2(a2[i][0], t.y, wa.y);
                fma2(a2[i][1], t.x, wb.x); fma2(a2[i][1], t.y, wb.y);
            }
        }
        __syncwarp();
#pragma unroll
        for (int i = 0; i < EB; i++) {
            float e0 = hsum2(a2[i][0]);
            float e1 = hsum2(a2[i][1]);
            scr[i * 64 + c0] = e0;
            scr[i * 64 + c1] = e1;
            g_e[(size_t)(base + i) * 64 + c0] = e0;
            g_e[(size_t)(base + i) * 64 + c1] = e1;
        }
        __syncwarp();

        // ================= stage 3: t2 = ssp(e' @ P1 + pb1) [64] =================
        u64 a3[EB][2];
#pragma unroll
        for (int i = 0; i < EB; i++) { a3[i][0] = pack2(q1v0, 0.f); a3[i][1] = pack2(q1v1, 0.f); }
#pragma unroll 2
        for (int k = 0; k < 64; k += 4) {
            ulonglong2 wa = *(const ulonglong2*)(p1p0 + k);
            ulonglong2 wb = *(const ulonglong2*)(p1p1 + k);
#pragma unroll
            for (int i = 0; i < EB; i++) {
                ulonglong2 t = *(const ulonglong2*)(scr + i * 64 + k);
                fma2(a3[i][0], t.x, wa.x); fma2(a3[i][0], t.y, wa.y);
                fma2(a3[i][1], t.x, wb.x); fma2(a3[i][1], t.y, wb.y);
            }
        }
        __syncwarp();
#pragma unroll
        for (int i = 0; i < EB; i++) {
            scr[512 + i * 64 + c0] = ssp_f(hsum2(a3[i][0]));
            scr[512 + i * 64 + c1] = ssp_f(hsum2(a3[i][1]));
        }
        __syncwarp();

        // ================= stage 4: he = t2 @ P2 + pb2; scatter-add =================
        u64 a4[EB][2];
#pragma unroll
        for (int i = 0; i < EB; i++) { a4[i][0] = pack2(q2v0, 0.f); a4[i][1] = pack2(q2v1, 0.f); }
#pragma unroll 2
        for (int k = 0; k < 64; k += 4) {
            ulonglong2 wa = *(const ulonglong2*)(p2p0 + k);
            ulonglong2 wb = *(const ulonglong2*)(p2p1 + k);
#pragma unroll
            for (int i = 0; i < EB; i++) {
                ulonglong2 t = *(const ulonglong2*)(scr + 512 + i * 64 + k);
                fma2(a4[i][0], t.x, wa.x); fma2(a4[i][0], t.y, wa.y);
                fma2(a4[i][1], t.x, wb.x); fma2(a4[i][1], t.y, wb.y);
            }
        }
#pragma unroll
        for (int i = 0; i < EB; i++) {
            float h0 = hsum2(a4[i][0]);
            float h1 = hsum2(a4[i][1]);
            float* dp = g_agg + (size_t)d[i] * 64;
            asm volatile("red.global.add.f32 [%0], %1;" :: "l"(dp + c0), "f"(h0) : "memory");
            asm volatile("red.global.add.f32 [%0], %1;" :: "l"(dp + c1), "f"(h1) : "memory");
        }
        __syncwarp();
    }
}

// ---------------- readout + per-graph mean ----------------
__global__ void __launch_bounds__(256) k_readout(
    const int* __restrict__ gid,
    const float* __restrict__ d1w, const float* __restrict__ d1b,
    const float* __restrict__ d2w, const float* __restrict__ d2b)
{
    __shared__ float sW[2048], sB1r[32], sW2r[32];
    __shared__ float sB2r;
    int tid = threadIdx.x;
    for (int i = tid; i < 2048; i += 256) sW[i] = d1w[i];
    if (tid < 32) { sB1r[tid] = d1b[tid]; sW2r[tid] = d2w[tid]; }
    if (tid == 0) sB2r = d2b[0];
    __syncthreads();
    int lane = tid & 31, warp = tid >> 5;
    int nw = gridDim.x * 8;
    for (int n = blockIdx.x * 8 + warp; n < NN; n += nw) {
        float2 hv = *(const float2*)(g_h + (size_t)n * 64 + 2 * lane);
        float a = sB1r[lane];
#pragma unroll 8
        for (int k = 0; k < 64; k++) {
            float ek = __shfl_sync(0xffffffffu, (k & 1) ? hv.y : hv.x, k >> 1);
            a = fmaf(ek, sW[k * 32 + lane], a);
        }
        float p = ssp_f(a) * sW2r[lane];
#pragma unroll
        for (int off = 16; off; off >>= 1) p += __shfl_xor_sync(0xffffffffu, p, off);
        if (lane == 0) {
            int g = gid[n];
            atomicAdd(&g_sums[g], p + sB2r);
            atomicAdd(&g_cnt[g], 1.0f);
        }
    }
}

__global__ void k_final(float* __restrict__ out) {
    int t = threadIdx.x;
    if (t < NG) out[t] = g_sums[t] / fmaxf(g_cnt[t], 1.0f);
}

// ---------------- launch ----------------
extern "C" void kernel_launch(void* const* d_in, const int* in_sizes, int n_in,
                              void* d_out, int out_size) {
    const int*   az     = (const int*)d_in[0];
    const float* dist   = (const float*)d_in[1];
    const int*   src    = (const int*)d_in[2];
    const int*   dst    = (const int*)d_in[3];
    const int*   gid    = (const int*)d_in[4];
    const float* emb    = (const float*)d_in[5];
    const float* eu_w1  = (const float*)d_in[6];
    const float* eu_b1  = (const float*)d_in[7];
    const float* eu_w2  = (const float*)d_in[8];
    const float* eu_b2  = (const float*)d_in[9];
    const float* pe1_w  = (const float*)d_in[10];
    const float* pe1_b  = (const float*)d_in[11];
    const float* pe2_w  = (const float*)d_in[12];
    const float* pe2_b  = (const float*)d_in[13];
    const float* pn2a_w = (const float*)d_in[14];
    const float* pn2a_b = (const float*)d_in[15];
    const float* pn2b_w = (const float*)d_in[16];
    const float* pn2b_b = (const float*)d_in[17];
    const float* d1w    = (const float*)d_in[18];
    const float* d1b    = (const float*)d_in[19];
    const float* d2w    = (const float*)d_in[20];
    const float* d2b    = (const float*)d_in[21];

    cudaFuncSetAttribute(k_edge,   cudaFuncAttributeMaxDynamicSharedMemorySize, EDGE_SMEM_FLOATS * 4);
    cudaFuncSetAttribute(k_update, cudaFuncAttributeMaxDynamicSharedMemorySize, UPD_SMEM_FLOATS * 4);
    cudaFuncSetAttribute(k_pre0,   cudaFuncAttributeMaxDynamicSharedMemorySize, 21504 * 4);

    k_init_nodes<<<(NN * 16 + 255) / 256, 256>>>(az, emb);
    k_init_edges<<<(NE * 64 + 255) / 256, 256>>>(dist);
    k_zero_pool<<<1, 256>>>();
    k_pre0<<<148, 512, 21504 * 4>>>(eu_w1);

    for (int l = 0; l < 3; l++) {
        k_edge<<<148, 512, EDGE_SMEM_FLOATS * 4>>>(
            src, dst,
            eu_w1 + (size_t)l * 24576 + 16384, eu_b1 + l * 128,
            eu_w2 + (size_t)l * 8192,          eu_b2 + l * 64,
            pe1_w + (size_t)l * 4096,          pe1_b + l * 64,
            pe2_w + (size_t)l * 4096,          pe2_b + l * 64);
        k_update<<<148, 512, UPD_SMEM_FLOATS * 4>>>(
            pn2a_w + (size_t)l * 4096, pn2a_b + l * 64,
            pn2b_w + (size_t)l * 4096, pn2b_b + l * 64,
            eu_w1 + (size_t)(l + 1) * 24576, (l < 2) ? 1 : 0);
    }
    k_readout<<<296, 256>>>(gid, d1w, d1b, d2w, d2b);
    k_final<<<1, 256>>>((float*)d_out);
}

// round 6
// speedup vs baseline: 4.1397x; 1.5211x over previous
#include <cuda_runtime.h>
#include <cuda_bf16.h>
#include <math.h>
#include <stdint.h>

#define NN 50000
#define NE 800000
#define NG 256
#define LN2F 0.69314718055994531f

// ---------------- scratch (device globals) ----------------
__device__ float g_h  [NN * 64];
__device__ float g_agg[NN * 64];
__device__ float g_e  [NE * 64];
__device__ float g_sums[NG];
__device__ float g_cnt [NG];
// pre-packed B fragments: 3 layers x 320 frags x 32 lanes (uint4 = {bh01,bh23,bl01,bl23})
__device__ uint4 g_frags[3 * 10240];

typedef unsigned long long u64;

__device__ __forceinline__ u64 pack2(float lo, float hi) {
    u64 r; asm("mov.b64 %0, {%1, %2};" : "=l"(r) : "f"(lo), "f"(hi)); return r;
}
__device__ __forceinline__ void fma2(u64 &d, u64 a, u64 b) {
    asm("fma.rn.f32x2 %0, %1, %2, %0;" : "+l"(d) : "l"(a), "l"(b));
}
__device__ __forceinline__ float hsum2(u64 v) {
    float lo, hi; asm("mov.b64 {%0, %1}, %2;" : "=f"(lo), "=f"(hi) : "l"(v));
    return lo + hi;
}
__device__ __forceinline__ float ssp_f(float x) {
    return fmaxf(x, 0.0f) + __logf(1.0f + __expf(-fabsf(x))) - LN2F;
}
// split two floats into bf16 hi pair + bf16 lo (residual) pair, packed b32 (first arg in low half)
__device__ __forceinline__ void bfsplit2(float a, float b, uint32_t &hi, uint32_t &lo) {
    __nv_bfloat16 ha = __float2bfloat16_rn(a), hb = __float2bfloat16_rn(b);
    hi = (uint32_t)__bfloat16_as_ushort(ha) | ((uint32_t)__bfloat16_as_ushort(hb) << 16);
    __nv_bfloat16 la = __float2bfloat16_rn(a - __bfloat162float(ha));
    __nv_bfloat16 lb = __float2bfloat16_rn(b - __bfloat162float(hb));
    lo = (uint32_t)__bfloat16_as_ushort(la) | ((uint32_t)__bfloat16_as_ushort(lb) << 16);
}

__device__ __forceinline__ void mma_bf16(float* c,
    uint32_t a0, uint32_t a1, uint32_t a2, uint32_t a3, uint32_t b0, uint32_t b1) {
    asm("mma.sync.aligned.m16n8k16.row.col.f32.bf16.bf16.f32 "
        "{%0,%1,%2,%3}, {%4,%5,%6,%7}, {%8,%9}, {%0,%1,%2,%3};"
        : "+f"(c[0]), "+f"(c[1]), "+f"(c[2]), "+f"(c[3])
        : "r"(a0), "r"(a1), "r"(a2), "r"(a3), "r"(b0), "r"(b1));
}

// ---------------- init ----------------
__global__ void k_init_nodes(const int* __restrict__ az, const float* __restrict__ emb) {
    int t = blockIdx.x * blockDim.x + threadIdx.x;
    if (t >= NN * 16) return;
    int n = t >> 4, q = t & 15;
    int z = az[n];
    float4 v = ((const float4*)(emb + (size_t)z * 64))[q];
    ((float4*)(g_h + (size_t)n * 64))[q] = v;
    ((float4*)(g_agg + (size_t)n * 64))[q] = make_float4(0.f, 0.f, 0.f, 0.f);
}

__global__ void k_init_edges(const float* __restrict__ dist) {
    int t = blockIdx.x * blockDim.x + threadIdx.x;
    if (t >= NE * 64) return;
    int e = t >> 6, j = t & 63;
    float d = dist[e];
    float c = (5.0f / 63.0f) * (float)j;
    float df = d - c;
    g_e[t] = __expf(-df * df * (63.0f / 5.0f));
}

__global__ void k_zero_pool() {
    int t = threadIdx.x;
    if (t < NG) { g_sums[t] = 0.f; g_cnt[t] = 0.f; }
}

// ---------------- weight fragment prep ----------------
// Fragment layout (per layer, 320 fragments):
//   [0,192):  W1 [192x128]  (12 ktiles x 16 ntiles)
//   [192,256): W2 [128x64]  (8 x 8)
//   [256,288): P1 [64x64]   (4 x 8)
//   [288,320): P2 [64x64]   (4 x 8)
// For fragment (kst, nt): lane holds B elems (k0,n),(k0+1,n),(k0+8,n),(k0+9,n)
// with n = nt*8 + (lane>>2), k0 = kst*16 + 2*(lane&3).
__global__ void k_prep(const float* __restrict__ eu_w1, const float* __restrict__ eu_w2,
                       const float* __restrict__ pe1_w, const float* __restrict__ pe2_w) {
    int s = blockIdx.x * blockDim.x + threadIdx.x;
    if (s >= 3 * 10240) return;
    int l = s / 10240, r = s % 10240;
    int f = r >> 5, lane = r & 31;
    const float* W; int NT, N, fl;
    if (f < 192)      { W = eu_w1 + (size_t)l * 24576; fl = f;       NT = 16; N = 128; }
    else if (f < 256) { W = eu_w2 + (size_t)l * 8192;  fl = f - 192; NT = 8;  N = 64; }
    else if (f < 288) { W = pe1_w + (size_t)l * 4096;  fl = f - 256; NT = 8;  N = 64; }
    else              { W = pe2_w + (size_t)l * 4096;  fl = f - 288; NT = 8;  N = 64; }
    int nt = fl % NT, kst = fl / NT;
    int n  = nt * 8 + (lane >> 2);
    int k0 = kst * 16 + 2 * (lane & 3);
    float w0 = W[(size_t)k0 * N + n];
    float w1 = W[(size_t)(k0 + 1) * N + n];
    float w2 = W[(size_t)(k0 + 8) * N + n];
    float w3 = W[(size_t)(k0 + 9) * N + n];
    uint32_t h01, l01, h23, l23;
    bfsplit2(w0, w1, h01, l01);
    bfsplit2(w2, w3, h23, l23);
    g_frags[s] = make_uint4(h01, h23, l01, l23);
}

// ---------------- smem layout for k_edge_mma ----------------
#define FRAG_U4   10240                 // 320 frags * 32 lanes
#define SM_BIAS1  (FRAG_U4 * 16)        // 163840 B : b1[128]
#define SM_BIAS2  (SM_BIAS1 + 512)      // b2[64]
#define SM_Q1     (SM_BIAS2 + 256)      // q1[64]
#define SM_Q2     (SM_Q1 + 256)         // q2[64]
#define EDGE_SMEM (SM_Q2 + 256)         // 165120 B

#define FR1 0
#define FR2 (192 * 32)
#define FR3 (256 * 32)
#define FR4 (288 * 32)

// ---------------- the mma.sync edge kernel ----------------
__global__ void __launch_bounds__(256, 1) k_edge_mma(
    int layer,
    const int* __restrict__ src, const int* __restrict__ dst,
    const float* __restrict__ b1, const float* __restrict__ b2,
    const float* __restrict__ pb1, const float* __restrict__ pb2)
{
    extern __shared__ char smem[];
    uint4* sm4 = (uint4*)smem;
    const int tid = threadIdx.x;

    // load weight fragments + biases
    {
        const uint4* srcf = g_frags + (size_t)layer * FRAG_U4;
        for (int i = tid; i < FRAG_U4; i += 256) sm4[i] = srcf[i];
        float* sB1 = (float*)(smem + SM_BIAS1);
        float* sB2 = (float*)(smem + SM_BIAS2);
        float* sQ1 = (float*)(smem + SM_Q1);
        float* sQ2 = (float*)(smem + SM_Q2);
        if (tid < 128) sB1[tid] = b1[tid];
        if (tid < 64) { sB2[tid] = b2[tid]; sQ1[tid] = pb1[tid]; sQ2[tid] = pb2[tid]; }
    }
    __syncthreads();

    const float* sB1f = (const float*)(smem + SM_BIAS1);
    const float* sB2f = (const float*)(smem + SM_BIAS2);
    const float* sQ1f = (const float*)(smem + SM_Q1);
    const float* sQ2f = (const float*)(smem + SM_Q2);

    const int wid = tid >> 5, lane = tid & 31;
    const int gr = lane >> 2;            // row group 0..7
    const int t2 = 2 * (lane & 3);       // col pair base

    const int NTILES = NE / 16;          // 50000
    const int wstride = gridDim.x * 8;

    for (int tile = blockIdx.x * 8 + wid; tile < NTILES; tile += wstride) {
        const int base = tile * 16;
        const int r0 = base + gr, r1 = base + gr + 8;
        const int is0 = __ldg(src + r0), is8 = __ldg(src + r1);
        const int id0 = __ldg(dst + r0), id8 = __ldg(dst + r1);

        // ============ stage 1: C1[16x128] = [hsrc|hdst|e] @ W1 ============
        float c1[16][4];
#pragma unroll
        for (int nt = 0; nt < 16; nt++) { c1[nt][0] = c1[nt][1] = c1[nt][2] = c1[nt][3] = 0.f; }

#pragma unroll 1
        for (int mat = 0; mat < 3; mat++) {
            const float *ra, *rb;
            if (mat == 0)      { ra = g_h + (size_t)is0 * 64; rb = g_h + (size_t)is8 * 64; }
            else if (mat == 1) { ra = g_h + (size_t)id0 * 64; rb = g_h + (size_t)id8 * 64; }
            else               { ra = g_e + (size_t)r0 * 64;  rb = g_e + (size_t)r1 * 64; }
#pragma unroll
            for (int kt = 0; kt < 4; kt++) {
                const int kk = kt * 16;
                float2 x0 = *(const float2*)(ra + kk + t2);
                float2 x1 = *(const float2*)(rb + kk + t2);
                float2 x2 = *(const float2*)(ra + kk + t2 + 8);
                float2 x3 = *(const float2*)(rb + kk + t2 + 8);
                uint32_t ah0, ah1, ah2, ah3, al0, al1, al2, al3;
                bfsplit2(x0.x, x0.y, ah0, al0);
                bfsplit2(x1.x, x1.y, ah1, al1);
                bfsplit2(x2.x, x2.y, ah2, al2);
                bfsplit2(x3.x, x3.y, ah3, al3);
                const uint4* fp = sm4 + FR1 + (size_t)(mat * 4 + kt) * 16 * 32 + lane;
#pragma unroll
                for (int nt = 0; nt < 16; nt++) {
                    uint4 f = fp[nt * 32];
                    mma_bf16(c1[nt], ah0, ah1, ah2, ah3, f.x, f.y);
                    mma_bf16(c1[nt], al0, al1, al2, al3, f.x, f.y);
                    mma_bf16(c1[nt], ah0, ah1, ah2, ah3, f.z, f.w);
                }
            }
        }

        // ============ epi 1: t1 = ssp(C1 + b1) -> A2 fragments (in reg) ============
        uint32_t a2h[8][4], a2l[8][4];
#pragma unroll
        for (int kt = 0; kt < 8; kt++) {
#pragma unroll
            for (int half = 0; half < 2; half++) {
                int nt = 2 * kt + half;
                float2 bb = *(const float2*)(sB1f + nt * 8 + t2);
                float v0 = ssp_f(c1[nt][0] + bb.x), v1 = ssp_f(c1[nt][1] + bb.y);
                float v2 = ssp_f(c1[nt][2] + bb.x), v3 = ssp_f(c1[nt][3] + bb.y);
                bfsplit2(v0, v1, a2h[kt][2 * half],     a2l[kt][2 * half]);
                bfsplit2(v2, v3, a2h[kt][2 * half + 1], a2l[kt][2 * half + 1]);
            }
        }

        // ============ stage 2: C2[16x64] = t1 @ W2 ============
        float c2[8][4];
#pragma unroll
        for (int nt = 0; nt < 8; nt++) { c2[nt][0] = c2[nt][1] = c2[nt][2] = c2[nt][3] = 0.f; }
#pragma unroll 1
        for (int kt = 0; kt < 8; kt++) {
            const uint4* fp = sm4 + FR2 + (size_t)kt * 8 * 32 + lane;
#pragma unroll
            for (int nt = 0; nt < 8; nt++) {
                uint4 f = fp[nt * 32];
                mma_bf16(c2[nt], a2h[kt][0], a2h[kt][1], a2h[kt][2], a2h[kt][3], f.x, f.y);
                mma_bf16(c2[nt], a2l[kt][0], a2l[kt][1], a2l[kt][2], a2l[kt][3], f.x, f.y);
                mma_bf16(c2[nt], a2h[kt][0], a2h[kt][1], a2h[kt][2], a2h[kt][3], f.z, f.w);
            }
        }

        // ============ epi 2: e' = C2 + b2 -> g_e, and A3 fragments ============
        uint32_t a3h[4][4], a3l[4][4];
        {
            float* er0 = g_e + (size_t)r0 * 64;
            float* er1 = g_e + (size_t)r1 * 64;
#pragma unroll
            for (int nt = 0; nt < 8; nt++) {
                float2 bb = *(const float2*)(sB2f + nt * 8 + t2);
                float x0 = c2[nt][0] + bb.x, x1 = c2[nt][1] + bb.y;
                float x2 = c2[nt][2] + bb.x, x3 = c2[nt][3] + bb.y;
                *(float2*)(er0 + nt * 8 + t2) = make_float2(x0, x1);
                *(float2*)(er1 + nt * 8 + t2) = make_float2(x2, x3);
                int kt = nt >> 1, half = nt & 1;
                bfsplit2(x0, x1, a3h[kt][2 * half],     a3l[kt][2 * half]);
                bfsplit2(x2, x3, a3h[kt][2 * half + 1], a3l[kt][2 * half + 1]);
            }
        }

        // ============ stage 3: C3 = e' @ P1 ============
        float c3[8][4];
#pragma unroll
        for (int nt = 0; nt < 8; nt++) { c3[nt][0] = c3[nt][1] = c3[nt][2] = c3[nt][3] = 0.f; }
#pragma unroll 1
        for (int kt = 0; kt < 4; kt++) {
            const uint4* fp = sm4 + FR3 + (size_t)kt * 8 * 32 + lane;
#pragma unroll
            for (int nt = 0; nt < 8; nt++) {
                uint4 f = fp[nt * 32];
                mma_bf16(c3[nt], a3h[kt][0], a3h[kt][1], a3h[kt][2], a3h[kt][3], f.x, f.y);
                mma_bf16(c3[nt], a3l[kt][0], a3l[kt][1], a3l[kt][2], a3l[kt][3], f.x, f.y);
                mma_bf16(c3[nt], a3h[kt][0], a3h[kt][1], a3h[kt][2], a3h[kt][3], f.z, f.w);
            }
        }

        // ============ epi 3: t2 = ssp(C3 + q1) -> A4 fragments ============
        uint32_t a4h[4][4], a4l[4][4];
#pragma unroll
        for (int nt = 0; nt < 8; nt++) {
            float2 bb = *(const float2*)(sQ1f + nt * 8 + t2);
            float v0 = ssp_f(c3[nt][0] + bb.x), v1 = ssp_f(c3[nt][1] + bb.y);
            float v2 = ssp_f(c3[nt][2] + bb.x), v3 = ssp_f(c3[nt][3] + bb.y);
            int kt = nt >> 1, half = nt & 1;
            bfsplit2(v0, v1, a4h[kt][2 * half],     a4l[kt][2 * half]);
            bfsplit2(v2, v3, a4h[kt][2 * half + 1], a4l[kt][2 * half + 1]);
        }

        // ============ stage 4: C4 = t2 @ P2 ============
        float c4[8][4];
#pragma unroll
        for (int nt = 0; nt < 8; nt++) { c4[nt][0] = c4[nt][1] = c4[nt][2] = c4[nt][3] = 0.f; }
#pragma unroll 1
        for (int kt = 0; kt < 4; kt++) {
            const uint4* fp = sm4 + FR4 + (size_t)kt * 8 * 32 + lane;
#pragma unroll
            for (int nt = 0; nt < 8; nt++) {
                uint4 f = fp[nt * 32];
                mma_bf16(c4[nt], a4h[kt][0], a4h[kt][1], a4h[kt][2], a4h[kt][3], f.x, f.y);
                mma_bf16(c4[nt], a4l[kt][0], a4l[kt][1], a4l[kt][2], a4l[kt][3], f.x, f.y);
                mma_bf16(c4[nt], a4h[kt][0], a4h[kt][1], a4h[kt][2], a4h[kt][3], f.z, f.w);
            }
        }

        // ============ epi 4: he = C4 + q2; scatter-add to g_agg[dst] ============
        {
            float* da = g_agg + (size_t)id0 * 64;
            float* db = g_agg + (size_t)id8 * 64;
#pragma unroll
            for (int nt = 0; nt < 8; nt++) {
                float2 bb = *(const float2*)(sQ2f + nt * 8 + t2);
                float x0 = c4[nt][0] + bb.x, x1 = c4[nt][1] + bb.y;
                float x2 = c4[nt][2] + bb.x, x3 = c4[nt][3] + bb.y;
                asm volatile("red.global.add.v2.f32 [%0], {%1, %2};"
                             :: "l"(da + nt * 8 + t2), "f"(x0), "f"(x1) : "memory");
                asm volatile("red.global.add.v2.f32 [%0], {%1, %2};"
                             :: "l"(db + nt * 8 + t2), "f"(x2), "f"(x3) : "memory");
            }
        }
    }
}

// ---------------- node update: h += ssp(agg@A+ba)@B + bb; agg=0 ----------------
#define UPD_SMEM_FLOATS 12928
__global__ void __launch_bounds__(512, 1) k_update(
    const float* __restrict__ wa, const float* __restrict__ ba,
    const float* __restrict__ wb, const float* __restrict__ bb_)
{
    extern __shared__ float sm[];
    float* sAT = sm;
    float* sBT = sm + 4352;
    float* sBa = sm + 8704;
    float* sBb = sm + 8768;
    float* sScr = sm + 8832;
    int tid = threadIdx.x;
    for (int i = tid; i < 4096; i += 512) {
        int k = i >> 6, c = i & 63;
        sAT[c * 68 + k] = wa[i];
        sBT[c * 68 + k] = wb[i];
    }
    if (tid < 64) { sBa[tid] = ba[tid]; sBb[tid] = bb_[tid]; }
    __syncthreads();

    int lane = tid & 31, warp = tid >> 5;
    float* scrN = sScr + warp * 256;
    const float bav0 = sBa[lane], bav1 = sBa[lane + 32];
    const float bbv0 = sBb[lane], bbv1 = sBb[lane + 32];
    const float* a0p = sAT + lane * 68;
    const float* a1p = sAT + (lane + 32) * 68;
    const float* b0p = sBT + lane * 68;
    const float* b1p = sBT + (lane + 32) * 68;
    const int stride = gridDim.x * 16;

    for (int g = blockIdx.x * 16 + warp; g < NN / 4; g += stride) {
        int n0 = g * 4;
        float4* av = (float4*)(g_agg + (size_t)n0 * 64);
        float4 z = make_float4(0.f, 0.f, 0.f, 0.f);
        float4 t0 = av[lane], t1v = av[lane + 32];
        ((float4*)scrN)[lane] = t0; ((float4*)scrN)[lane + 32] = t1v;
        av[lane] = z; av[lane + 32] = z;
        __syncwarp();
        u64 aa[4][2];
#pragma unroll
        for (int i = 0; i < 4; i++) { aa[i][0] = pack2(bav0, 0.f); aa[i][1] = pack2(bav1, 0.f); }
#pragma unroll 4
        for (int k = 0; k < 64; k += 4) {
            ulonglong2 w0 = *(const ulonglong2*)(a0p + k);
            ulonglong2 w1 = *(const ulonglong2*)(a1p + k);
#pragma unroll
            for (int i = 0; i < 4; i++) {
                ulonglong2 tt = *(const ulonglong2*)(scrN + i * 64 + k);
                fma2(aa[i][0], tt.x, w0.x); fma2(aa[i][0], tt.y, w0.y);
                fma2(aa[i][1], tt.x, w1.x); fma2(aa[i][1], tt.y, w1.y);
            }
        }
        __syncwarp();
#pragma unroll
        for (int i = 0; i < 4; i++) {
            scrN[i * 64 + lane]      = ssp_f(hsum2(aa[i][0]));
            scrN[i * 64 + lane + 32] = ssp_f(hsum2(aa[i][1]));
        }
        __syncwarp();
        u64 oo[4][2];
#pragma unroll
        for (int i = 0; i < 4; i++) { oo[i][0] = pack2(bbv0, 0.f); oo[i][1] = pack2(bbv1, 0.f); }
#pragma unroll 4
        for (int k = 0; k < 64; k += 4) {
            ulonglong2 w0 = *(const ulonglong2*)(b0p + k);
            ulonglong2 w1 = *(const ulonglong2*)(b1p + k);
#pragma unroll
            for (int i = 0; i < 4; i++) {
                ulonglong2 tt = *(const ulonglong2*)(scrN + i * 64 + k);
                fma2(oo[i][0], tt.x, w0.x); fma2(oo[i][0], tt.y, w0.y);
                fma2(oo[i][1], tt.x, w1.x); fma2(oo[i][1], tt.y, w1.y);
            }
        }
        __syncwarp();
#pragma unroll
        for (int i = 0; i < 4; i++) {
            float* hp = g_h + (size_t)(n0 + i) * 64;
            hp[lane]      += hsum2(oo[i][0]);
            hp[lane + 32] += hsum2(oo[i][1]);
        }
        __syncwarp();
    }
}

// ---------------- readout + per-graph mean ----------------
__global__ void __launch_bounds__(256) k_readout(
    const int* __restrict__ gid,
    const float* __restrict__ d1w, const float* __restrict__ d1b,
    const float* __restrict__ d2w, const float* __restrict__ d2b)
{
    __shared__ float sW[2048], sB1r[32], sW2r[32];
    __shared__ float sB2r;
    int tid = threadIdx.x;
    for (int i = tid; i < 2048; i += 256) sW[i] = d1w[i];
    if (tid < 32) { sB1r[tid] = d1b[tid]; sW2r[tid] = d2w[tid]; }
    if (tid == 0) sB2r = d2b[0];
    __syncthreads();
    int lane = tid & 31, warp = tid >> 5;
    int nw = gridDim.x * 8;
    for (int n = blockIdx.x * 8 + warp; n < NN; n += nw) {
        float2 hv = *(const float2*)(g_h + (size_t)n * 64 + 2 * lane);
        float a = sB1r[lane];
#pragma unroll 8
        for (int k = 0; k < 64; k++) {
            float ek = __shfl_sync(0xffffffffu, (k & 1) ? hv.y : hv.x, k >> 1);
            a = fmaf(ek, sW[k * 32 + lane], a);
        }
        float p = ssp_f(a) * sW2r[lane];
#pragma unroll
        for (int off = 16; off; off >>= 1) p += __shfl_xor_sync(0xffffffffu, p, off);
        if (lane == 0) {
            int g = gid[n];
            atomicAdd(&g_sums[g], p + sB2r);
            atomicAdd(&g_cnt[g], 1.0f);
        }
    }
}

__global__ void k_final(float* __restrict__ out) {
    int t = threadIdx.x;
    if (t < NG) out[t] = g_sums[t] / fmaxf(g_cnt[t], 1.0f);
}

// ---------------- launch ----------------
extern "C" void kernel_launch(void* const* d_in, const int* in_sizes, int n_in,
                              void* d_out, int out_size) {
    const int*   az     = (const int*)d_in[0];
    const float* dist   = (const float*)d_in[1];
    const int*   src    = (const int*)d_in[2];
    const int*   dst    = (const int*)d_in[3];
    const int*   gid    = (const int*)d_in[4];
    const float* emb    = (const float*)d_in[5];
    const float* eu_w1  = (const float*)d_in[6];
    const float* eu_b1  = (const float*)d_in[7];
    const float* eu_w2  = (const float*)d_in[8];
    const float* eu_b2  = (const float*)d_in[9];
    const float* pe1_w  = (const float*)d_in[10];
    const float* pe1_b  = (const float*)d_in[11];
    const float* pe2_w  = (const float*)d_in[12];
    const float* pe2_b  = (const float*)d_in[13];
    const float* pn2a_w = (const float*)d_in[14];
    const float* pn2a_b = (const float*)d_in[15];
    const float* pn2b_w = (const float*)d_in[16];
    const float* pn2b_b = (const float*)d_in[17];
    const float* d1w    = (const float*)d_in[18];
    const float* d1b    = (const float*)d_in[19];
    const float* d2w    = (const float*)d_in[20];
    const float* d2b    = (const float*)d_in[21];

    cudaFuncSetAttribute(k_edge_mma, cudaFuncAttributeMaxDynamicSharedMemorySize, EDGE_SMEM);
    cudaFuncSetAttribute(k_update,   cudaFuncAttributeMaxDynamicSharedMemorySize, UPD_SMEM_FLOATS * 4);

    k_init_nodes<<<(NN * 16 + 255) / 256, 256>>>(az, emb);
    k_init_edges<<<(NE * 64 + 255) / 256, 256>>>(dist);
    k_zero_pool<<<1, 256>>>();
    k_prep<<<(3 * 10240 + 255) / 256, 256>>>(eu_w1, eu_w2, pe1_w, pe2_w);

    for (int l = 0; l < 3; l++) {
        k_edge_mma<<<148, 256, EDGE_SMEM>>>(
            l, src, dst,
            eu_b1 + l * 128, eu_b2 + l * 64,
            pe1_b + l * 64,  pe2_b + l * 64);
        k_update<<<148, 512, UPD_SMEM_FLOATS * 4>>>(
            pn2a_w + (size_t)l * 4096, pn2a_b + l * 64,
            pn2b_w + (size_t)l * 4096, pn2b_b + l * 64);
    }
    k_readout<<<296, 256>>>(gid, d1w, d1b, d2w, d2b);
    k_final<<<1, 256>>>((float*)d_out);
}